// round 1
// baseline (speedup 1.0000x reference)
#include <cuda_runtime.h>
#include <math.h>

#define BB 2
#define SS 2048
#define HH 3584
#define NH 28
#define NKV 4
#define HD 128
#define QSZ (NH*HD)            // 3584
#define KVSZ (NKV*HD)          // 512
#define QKVSZ (QSZ + 2*KVSZ)   // 4608
#define NT (BB*SS)             // 4096

// Scratch (no cudaMalloc allowed)
__device__ float g_qkv[(size_t)NT * QKVSZ];   // ~75.5 MB
__device__ float g_attn[(size_t)NT * QSZ];    // ~58.7 MB
__device__ float g_cos[SS * 64];
__device__ float g_sin[SS * 64];

// ---------------------------------------------------------------------------
// RoPE tables, computed in fp64 for angle accuracy (pos up to 2047)
// ---------------------------------------------------------------------------
__global__ void rope_table_kernel(float* __restrict__ ct, float* __restrict__ st) {
    int p = blockIdx.x;      // position 0..SS-1
    int d = threadIdx.x;     // 0..63
    double inv = exp(((double)(-2 * d) / 128.0) * log(1000000.0));
    double a = (double)p * inv;
    ct[p * 64 + d] = (float)cos(a);
    st[p * 64 + d] = (float)sin(a);
}

// ---------------------------------------------------------------------------
// In-place neox RoPE on q and k sections of g_qkv
// grid: (NT, NH+NKV), block: 64
// ---------------------------------------------------------------------------
__global__ void rope_kernel(float* __restrict__ qkv, const int* __restrict__ pos,
                            const float* __restrict__ ct, const float* __restrict__ st) {
    int t = blockIdx.x;
    int hh = blockIdx.y;    // 0..27 => q head, 28..31 => k head
    int d = threadIdx.x;    // 0..63
    int p = pos[t];
    float c = ct[p * 64 + d];
    float s = st[p * 64 + d];
    float* base = qkv + (size_t)t * QKVSZ +
                  (hh < NH ? hh * HD : QSZ + (hh - NH) * HD);
    float x1 = base[d];
    float x2 = base[d + 64];
    base[d]      = x1 * c - x2 * s;
    base[d + 64] = x2 * c + x1 * s;
}

// ---------------------------------------------------------------------------
// 128x128x8 SGEMM, C = A[MxK] @ B[KxN] (+ bias), row-major, all dims multiples
// of tile sizes for this problem. 256 threads, 8x8 per thread, prefetched.
// ---------------------------------------------------------------------------
__global__ __launch_bounds__(256) void sgemm_bias(
    const float* __restrict__ A, const float* __restrict__ Bm,
    const float* __restrict__ bias, float* __restrict__ C,
    int M, int N, int K)
{
    __shared__ float As[8][132];
    __shared__ float Bs[8][132];
    int tid = threadIdx.x;
    int ty = tid >> 4, tx = tid & 15;
    int bm = blockIdx.y * 128, bn = blockIdx.x * 128;

    int arow = tid >> 1, akq = (tid & 1) << 2;        // A tile: 128 rows x 8 k
    int brow = tid >> 5, bcol = (tid & 31) << 2;      // B tile: 8 rows x 128 n

    const float* Ap = A + (size_t)(bm + arow) * K + akq;
    const float* Bp = Bm + (size_t)brow * N + bn + bcol;

    float acc[8][8];
#pragma unroll
    for (int i = 0; i < 8; i++)
#pragma unroll
        for (int j = 0; j < 8; j++) acc[i][j] = 0.f;

    float4 av = *(const float4*)Ap;
    float4 bv = *(const float4*)Bp;

    for (int k0 = 0; k0 < K; k0 += 8) {
        As[akq + 0][arow] = av.x;
        As[akq + 1][arow] = av.y;
        As[akq + 2][arow] = av.z;
        As[akq + 3][arow] = av.w;
        *(float4*)&Bs[brow][bcol] = bv;
        __syncthreads();

        if (k0 + 8 < K) {
            av = *(const float4*)(Ap + k0 + 8);
            bv = *(const float4*)(Bp + (size_t)(k0 + 8) * N);
        }

#pragma unroll
        for (int kk = 0; kk < 8; kk++) {
            float a[8], b[8];
            *(float4*)(a)     = *(const float4*)&As[kk][ty * 8];
            *(float4*)(a + 4) = *(const float4*)&As[kk][ty * 8 + 4];
            *(float4*)(b)     = *(const float4*)&Bs[kk][tx * 8];
            *(float4*)(b + 4) = *(const float4*)&Bs[kk][tx * 8 + 4];
#pragma unroll
            for (int i = 0; i < 8; i++)
#pragma unroll
                for (int j = 0; j < 8; j++)
                    acc[i][j] = fmaf(a[i], b[j], acc[i][j]);
        }
        __syncthreads();
    }

#pragma unroll
    for (int i = 0; i < 8; i++) {
        int r = bm + ty * 8 + i;
        float* Cp = C + (size_t)r * N + bn + tx * 8;
#pragma unroll
        for (int j = 0; j < 8; j++) {
            float v = acc[i][j];
            if (bias) v += bias[bn + tx * 8 + j];
            Cp[j] = v;
        }
    }
}

// ---------------------------------------------------------------------------
// Flash attention: 64 queries x 64 keys per inner step, D=128, causal, GQA.
// grid: (SS/64, NH, BB), block 256. Dynamic smem 115712 B.
// Thread (ty,tx): score rows qr=ty+16i (i<4), cols kc=tx+16j (j<4);
// O accumulator rows qr, cols tx*8..tx*8+7.
// ---------------------------------------------------------------------------
__global__ __launch_bounds__(256) void flash_kernel(
    const float* __restrict__ qkv, float* __restrict__ attn)
{
    extern __shared__ float smf[];
    float* Qs = smf;                 // [64][128]
    float* Ks = Qs + 64 * 128;       // [64][132] padded
    float* Vs = Ks + 64 * 132;       // [64][128]
    float* Ps = Vs + 64 * 128;       // [64][64]

    int qb = blockIdx.x, h = blockIdx.y, b = blockIdx.z;
    int kvh = h / (NH / NKV);
    int tid = threadIdx.x;
    int ty = tid >> 4, tx = tid & 15;
    const float scale = 0.08838834764831845f;  // 1/sqrt(128)

    // load Q tile
#pragma unroll
    for (int it = 0; it < 8; it++) {
        int idx = tid + it * 256;
        int r = idx >> 5;
        int d4 = (idx & 31) << 2;
        *(float4*)&Qs[r * 128 + d4] =
            *(const float4*)(qkv + (size_t)(b * SS + qb * 64 + r) * QKVSZ + h * HD + d4);
    }

    float m[4], l[4], o[4][8];
#pragma unroll
    for (int i = 0; i < 4; i++) {
        m[i] = -INFINITY;
        l[i] = 0.f;
#pragma unroll
        for (int c = 0; c < 8; c++) o[i][c] = 0.f;
    }

    for (int kb = 0; kb <= qb; kb++) {
        __syncthreads();  // prev iter's Ps/Vs reads done; also covers Q load on kb=0
#pragma unroll
        for (int it = 0; it < 8; it++) {
            int idx = tid + it * 256;
            int r = idx >> 5;
            int d4 = (idx & 31) << 2;
            size_t base = (size_t)(b * SS + kb * 64 + r) * QKVSZ + QSZ + kvh * HD;
            *(float4*)&Ks[r * 132 + d4] = *(const float4*)(qkv + base + d4);
            *(float4*)&Vs[r * 128 + d4] = *(const float4*)(qkv + base + KVSZ + d4);
        }
        __syncthreads();

        float sc[4][4];
#pragma unroll
        for (int i = 0; i < 4; i++)
#pragma unroll
            for (int j = 0; j < 4; j++) sc[i][j] = 0.f;

        for (int d = 0; d < HD; d += 4) {
            float4 q[4], k[4];
#pragma unroll
            for (int i = 0; i < 4; i++)
                q[i] = *(const float4*)&Qs[(ty + 16 * i) * 128 + d];
#pragma unroll
            for (int j = 0; j < 4; j++)
                k[j] = *(const float4*)&Ks[(tx + 16 * j) * 132 + d];
#pragma unroll
            for (int i = 0; i < 4; i++)
#pragma unroll
                for (int j = 0; j < 4; j++) {
                    sc[i][j] = fmaf(q[i].x, k[j].x, sc[i][j]);
                    sc[i][j] = fmaf(q[i].y, k[j].y, sc[i][j]);
                    sc[i][j] = fmaf(q[i].z, k[j].z, sc[i][j]);
                    sc[i][j] = fmaf(q[i].w, k[j].w, sc[i][j]);
                }
        }

        bool diag = (kb == qb);
#pragma unroll
        for (int i = 0; i < 4; i++) {
#pragma unroll
            for (int j = 0; j < 4; j++) {
                sc[i][j] *= scale;
                if (diag && (tx + 16 * j) > (ty + 16 * i)) sc[i][j] = -INFINITY;
            }
            float mm = fmaxf(fmaxf(sc[i][0], sc[i][1]), fmaxf(sc[i][2], sc[i][3]));
            mm = fmaxf(mm, __shfl_xor_sync(0xffffffffu, mm, 1));
            mm = fmaxf(mm, __shfl_xor_sync(0xffffffffu, mm, 2));
            mm = fmaxf(mm, __shfl_xor_sync(0xffffffffu, mm, 4));
            mm = fmaxf(mm, __shfl_xor_sync(0xffffffffu, mm, 8));
            float mnew = fmaxf(m[i], mm);
            float alpha = expf(m[i] - mnew);   // 0 on first block (m=-inf)
            float ps = 0.f;
#pragma unroll
            for (int j = 0; j < 4; j++) {
                float p = expf(sc[i][j] - mnew);  // masked -> exp(-inf)=0
                Ps[(ty + 16 * i) * 64 + tx + 16 * j] = p;
                ps += p;
            }
            ps += __shfl_xor_sync(0xffffffffu, ps, 1);
            ps += __shfl_xor_sync(0xffffffffu, ps, 2);
            ps += __shfl_xor_sync(0xffffffffu, ps, 4);
            ps += __shfl_xor_sync(0xffffffffu, ps, 8);
            l[i] = l[i] * alpha + ps;
            m[i] = mnew;
#pragma unroll
            for (int c = 0; c < 8; c++) o[i][c] *= alpha;
        }
        __syncthreads();  // Ps ready for all threads

#pragma unroll 4
        for (int kc = 0; kc < 64; kc++) {
            float4 v0 = *(const float4*)&Vs[kc * 128 + tx * 8];
            float4 v1 = *(const float4*)&Vs[kc * 128 + tx * 8 + 4];
#pragma unroll
            for (int i = 0; i < 4; i++) {
                float p = Ps[(ty + 16 * i) * 64 + kc];
                o[i][0] = fmaf(p, v0.x, o[i][0]);
                o[i][1] = fmaf(p, v0.y, o[i][1]);
                o[i][2] = fmaf(p, v0.z, o[i][2]);
                o[i][3] = fmaf(p, v0.w, o[i][3]);
                o[i][4] = fmaf(p, v1.x, o[i][4]);
                o[i][5] = fmaf(p, v1.y, o[i][5]);
                o[i][6] = fmaf(p, v1.z, o[i][6]);
                o[i][7] = fmaf(p, v1.w, o[i][7]);
            }
        }
    }

#pragma unroll
    for (int i = 0; i < 4; i++) {
        float inv = 1.0f / l[i];
        int t = b * SS + qb * 64 + ty + 16 * i;
        float* dst = attn + (size_t)t * QSZ + h * HD + tx * 8;
#pragma unroll
        for (int c = 0; c < 8; c++) dst[c] = o[i][c] * inv;
    }
}

// ---------------------------------------------------------------------------
// Inputs (metadata order): hidden_states f32[B,S,H], positions i32[B,S],
// Wqkv f32[H, Q+2KV], bqkv f32[Q+2KV], Wo f32[Q, H]. Output f32[B,S,H].
// ---------------------------------------------------------------------------
extern "C" void kernel_launch(void* const* d_in, const int* in_sizes, int n_in,
                              void* d_out, int out_size)
{
    (void)in_sizes; (void)n_in; (void)out_size;
    const float* hidden    = (const float*)d_in[0];
    const int*   positions = (const int*)d_in[1];
    const float* Wqkv      = (const float*)d_in[2];
    const float* bqkv      = (const float*)d_in[3];
    const float* Wo        = (const float*)d_in[4];
    float* out = (float*)d_out;

    float *qkv, *attn, *ct, *st;
    cudaGetSymbolAddress((void**)&qkv,  g_qkv);
    cudaGetSymbolAddress((void**)&attn, g_attn);
    cudaGetSymbolAddress((void**)&ct,   g_cos);
    cudaGetSymbolAddress((void**)&st,   g_sin);

    const int flash_smem = (64 * 128 + 64 * 132 + 64 * 128 + 64 * 64) * 4; // 115712
    cudaFuncSetAttribute(flash_kernel,
                         cudaFuncAttributeMaxDynamicSharedMemorySize, flash_smem);

    // 1. RoPE cos/sin tables
    rope_table_kernel<<<SS, 64>>>(ct, st);

    // 2. QKV projection + bias
    dim3 g1(QKVSZ / 128, NT / 128);  // (36, 32)
    sgemm_bias<<<g1, 256>>>(hidden, Wqkv, bqkv, qkv, NT, QKVSZ, HH);

    // 3. RoPE on q and k
    dim3 gr(NT, NH + NKV);
    rope_kernel<<<gr, 64>>>(qkv, positions, ct, st);

    // 4. Causal GQA flash attention
    dim3 gf(SS / 64, NH, BB);
    flash_kernel<<<gf, 256, flash_smem>>>(qkv, attn);

    // 5. Output projection
    dim3 g2(HH / 128, NT / 128);  // (28, 32)
    sgemm_bias<<<g2, 256>>>(attn, Wo, nullptr, out, NT, HH, HH);
}